// round 2
// baseline (speedup 1.0000x reference)
#include <cuda_runtime.h>
#include <cuda_bf16.h>
#include <cstdint>

// Problem constants
#define BB    256        // batch
#define NE    1024
#define NTOT  2048       // combined E+I
#define DD    256        // input dim
#define STEPS 200
#define LASTN 50

// ---------------- device scratch (no allocations allowed) ----------------
__device__ __nv_bfloat16 g_Whi[NTOT * NTOT];   // combined scaled weights, hi part
__device__ __nv_bfloat16 g_Wlo[NTOT * NTOT];   // lo part
__device__ float g_Iff[BB * NTOT];             // feed-forward currents
__device__ float g_r[2][BB * NTOT];            // double-buffered state
__device__ float g_acc[BB * NTOT];             // accumulator of last 50 states

// ---------------- weight preparation ----------------
// Combined W[j][k]: j<1024 -> row of [min(W_EE,0.15)*gE_E , -max(W_EI,5e-4)*gI_E]
//                   j>=1024 -> row of [W_IE*gE_I , -W_II*gI_I]
// g_* = S / (rowsum(raw) + 1e-12), rowsum of UNclamped raw weights.
__global__ void prep_w_kernel(const float* __restrict__ WEE,
                              const float* __restrict__ WEI,
                              const float* __restrict__ WIE,
                              const float* __restrict__ WII) {
    __shared__ float red[256];
    int j = blockIdx.x;
    int tid = threadIdx.x;
    bool isE = (j < NE);
    const float* rawA;
    const float* rawB;
    float SA, SB;
    if (isE) {
        rawA = WEE + (size_t)j * NE;  SA = 3.75f;
        rawB = WEI + (size_t)j * NE;  SB = 1.86f;
    } else {
        int j2 = j - NE;
        rawA = WIE + (size_t)j2 * NE; SA = 3.13f;
        rawB = WII + (size_t)j2 * NE; SB = 1.11f - 0.02f;
    }
    float sA = 0.f, sB = 0.f;
    for (int k = tid; k < NE; k += 256) { sA += rawA[k]; sB += rawB[k]; }
    red[tid] = sA; __syncthreads();
    for (int s = 128; s > 0; s >>= 1) { if (tid < s) red[tid] += red[tid + s]; __syncthreads(); }
    float sumA = red[0]; __syncthreads();
    red[tid] = sB; __syncthreads();
    for (int s = 128; s > 0; s >>= 1) { if (tid < s) red[tid] += red[tid + s]; __syncthreads(); }
    float sumB = red[0];

    float gA = SA / (sumA + 1e-12f);
    float gB = SB / (sumB + 1e-12f);

    for (int k = tid; k < NE; k += 256) {
        float a = rawA[k];
        if (isE) a = fminf(a, 0.15f);
        a *= gA;
        __nv_bfloat16 ha = __float2bfloat16_rn(a);
        g_Whi[j * NTOT + k] = ha;
        g_Wlo[j * NTOT + k] = __float2bfloat16_rn(a - __bfloat162float(ha));

        float b = rawB[k];
        if (isE) b = fmaxf(b, 0.0005f);
        b = -b * gB;
        __nv_bfloat16 hb = __float2bfloat16_rn(b);
        g_Whi[j * NTOT + NE + k] = hb;
        g_Wlo[j * NTOT + NE + k] = __float2bfloat16_rn(b - __bfloat162float(hb));
    }
}

// ---------------- feed-forward currents: Iff[b][j] = sum_d x[b][d]*Wff[j][d] --
// block: 256 threads handle 256 consecutive j for a 16-row b tile.
__global__ void iff_kernel(const float* __restrict__ x,
                           const float* __restrict__ WffE,
                           const float* __restrict__ WffI) {
    __shared__ float sx[16][DD];
    int tid = threadIdx.x;
    int jblk = blockIdx.x * 256;
    int bblk = blockIdx.y * 16;
    for (int i = 0; i < 16; i++) sx[i][tid] = x[(bblk + i) * DD + tid];
    __syncthreads();
    int j = jblk + tid;
    const float* wr = (j < NE) ? (WffE + (size_t)j * DD) : (WffI + (size_t)(j - NE) * DD);
    float acc[16];
#pragma unroll
    for (int b = 0; b < 16; b++) acc[b] = 0.f;
    for (int d = 0; d < DD; d++) {
        float wv = __ldg(wr + d);
#pragma unroll
        for (int b = 0; b < 16; b++) acc[b] += sx[b][d] * wv;
    }
    for (int b = 0; b < 16; b++) g_Iff[(bblk + b) * NTOT + j] = acc[b];
}

// ---------------- zero init (must run every launch: graph replays) ----------
__global__ void zero_kernel() {
    int i = blockIdx.x * blockDim.x + threadIdx.x;
    int stride = gridDim.x * blockDim.x;
    for (int k = i; k < BB * NTOT; k += stride) {
        g_r[0][k] = 0.f;
        g_r[1][k] = 0.f;
        g_acc[k] = 0.f;
    }
}

// ---------------- bf16 mma helper ----------------
__device__ __forceinline__ void mma_bf16(float* c, const uint32_t* a, const uint32_t* b) {
    asm volatile(
        "mma.sync.aligned.m16n8k16.row.col.f32.bf16.bf16.f32 "
        "{%0,%1,%2,%3}, {%4,%5,%6,%7}, {%8,%9}, {%0,%1,%2,%3};\n"
        : "+f"(c[0]), "+f"(c[1]), "+f"(c[2]), "+f"(c[3])
        : "r"(a[0]), "r"(a[1]), "r"(a[2]), "r"(a[3]), "r"(b[0]), "r"(b[1]));
}

// ---------------- one dynamics step (fused GEMM + pointwise update) ---------
// I = Iff + r @ W^T  (split-bf16, 3-product, fp32 accumulate)
// r' = r + rate*(f(I) - r),  f(I)=0.04*relu(I)^2, rate = 0.05 (E) / 0.1 (I)
// CTA tile 64(M=batch) x 64(N=neurons), 4 warps (2x2), warp tile 32x32.
__global__ __launch_bounds__(128, 1) void step_kernel(int parity, int t) {
    const float* __restrict__ rin = g_r[parity];
    float* __restrict__ rout = g_r[parity ^ 1];

    __shared__ __nv_bfloat16 sAhi[64][36], sAlo[64][36];
    __shared__ __nv_bfloat16 sBhi[64][36], sBlo[64][36];

    int tid = threadIdx.x;
    int n0 = blockIdx.x * 64;   // neuron tile
    int m0 = blockIdx.y * 64;   // batch tile
    int warp = tid >> 5, lane = tid & 31;
    int wm = (warp >> 1) << 5;  // warp M offset (0/32)
    int wn = (warp & 1) << 5;   // warp N offset (0/32)
    int g = lane >> 2, tg = lane & 3;

    float acc[2][4][4];
#pragma unroll
    for (int mt = 0; mt < 2; mt++)
#pragma unroll
        for (int nt = 0; nt < 4; nt++)
#pragma unroll
            for (int q = 0; q < 4; q++) acc[mt][nt][q] = 0.f;

    const uint32_t* ph = (const uint32_t*)g_Whi;
    const uint32_t* pl = (const uint32_t*)g_Wlo;

    for (int k0 = 0; k0 < NTOT; k0 += 32) {
        // A tile: 64x32 fp32 state -> split hi/lo bf16
#pragma unroll
        for (int i = 0; i < 16; i++) {
            int idx = tid + (i << 7);
            int r = idx >> 5, c = idx & 31;
            float v = rin[(m0 + r) * NTOT + k0 + c];
            __nv_bfloat16 h = __float2bfloat16_rn(v);
            sAhi[r][c] = h;
            sAlo[r][c] = __float2bfloat16_rn(v - __bfloat162float(h));
        }
        // B tile: 64x32 bf16 weights (already split)
#pragma unroll
        for (int i = 0; i < 8; i++) {
            int idx = tid + (i << 7);
            int r = idx >> 4, cp = idx & 15;
            int off = (((n0 + r) * NTOT + k0) >> 1) + cp;
            *(uint32_t*)&sBhi[r][cp << 1] = __ldg(ph + off);
            *(uint32_t*)&sBlo[r][cp << 1] = __ldg(pl + off);
        }
        __syncthreads();

#pragma unroll
        for (int ks = 0; ks < 2; ks++) {
            int kb = ks << 4;
            uint32_t ah[2][4], al[2][4], bh[4][2], bl[4][2];
#pragma unroll
            for (int mt = 0; mt < 2; mt++) {
                int r0 = wm + (mt << 4) + g;
                int c0 = kb + (tg << 1);
                ah[mt][0] = *(const uint32_t*)&sAhi[r0][c0];
                ah[mt][1] = *(const uint32_t*)&sAhi[r0 + 8][c0];
                ah[mt][2] = *(const uint32_t*)&sAhi[r0][c0 + 8];
                ah[mt][3] = *(const uint32_t*)&sAhi[r0 + 8][c0 + 8];
                al[mt][0] = *(const uint32_t*)&sAlo[r0][c0];
                al[mt][1] = *(const uint32_t*)&sAlo[r0 + 8][c0];
                al[mt][2] = *(const uint32_t*)&sAlo[r0][c0 + 8];
                al[mt][3] = *(const uint32_t*)&sAlo[r0 + 8][c0 + 8];
            }
#pragma unroll
            for (int nt = 0; nt < 4; nt++) {
                int nr = wn + (nt << 3) + g;
                int c0 = kb + (tg << 1);
                bh[nt][0] = *(const uint32_t*)&sBhi[nr][c0];
                bh[nt][1] = *(const uint32_t*)&sBhi[nr][c0 + 8];
                bl[nt][0] = *(const uint32_t*)&sBlo[nr][c0];
                bl[nt][1] = *(const uint32_t*)&sBlo[nr][c0 + 8];
            }
#pragma unroll
            for (int mt = 0; mt < 2; mt++)
#pragma unroll
                for (int nt = 0; nt < 4; nt++) {
                    mma_bf16(acc[mt][nt], ah[mt], bh[nt]);
                    mma_bf16(acc[mt][nt], ah[mt], bl[nt]);
                    mma_bf16(acc[mt][nt], al[mt], bh[nt]);
                }
        }
        __syncthreads();
    }

    // epilogue: I = acc + Iff; power-law; Euler update; accumulate last 50
#pragma unroll
    for (int mt = 0; mt < 2; mt++) {
#pragma unroll
        for (int nt = 0; nt < 4; nt++) {
            int row0 = m0 + wm + (mt << 4) + g;
            int col0 = n0 + wn + (nt << 3) + (tg << 1);
#pragma unroll
            for (int q = 0; q < 4; q++) {
                int b = row0 + ((q >> 1) << 3);
                int j = col0 + (q & 1);
                int idx = b * NTOT + j;
                float I = acc[mt][nt][q] + g_Iff[idx];
                float rl = fmaxf(I, 0.f);
                float f = 0.04f * rl * rl;
                float ro = rin[idx];
                float rate = (j < NE) ? 0.05f : 0.1f;
                float rn2 = fmaf(rate, f - ro, ro);
                rout[idx] = rn2;
                if (t >= STEPS - LASTN) g_acc[idx] += rn2;
            }
        }
    }
}

// ---------------- finalize: out = [rE_bar (256x1024), rI_bar (256x1024)] -----
__global__ void fin_kernel(float* __restrict__ out) {
    int i = blockIdx.x * blockDim.x + threadIdx.x;
    if (i < BB * NTOT) {
        int b = i >> 11;       // /2048
        int j = i & 2047;
        float v = g_acc[i] * (1.0f / (float)LASTN);
        if (j < NE) out[b * NE + j] = v;
        else        out[BB * NE + b * NE + (j - NE)] = v;
    }
}

// ---------------- launch ----------------
extern "C" void kernel_launch(void* const* d_in, const int* in_sizes, int n_in,
                              void* d_out, int out_size) {
    const float* x    = (const float*)d_in[0];
    const float* WEE  = (const float*)d_in[1];
    const float* WEI  = (const float*)d_in[2];
    const float* WIE  = (const float*)d_in[3];
    const float* WII  = (const float*)d_in[4];
    const float* WffE = (const float*)d_in[5];
    const float* WffI = (const float*)d_in[6];
    float* out = (float*)d_out;

    prep_w_kernel<<<NTOT, 256>>>(WEE, WEI, WIE, WII);
    iff_kernel<<<dim3(NTOT / 256, BB / 16), 256>>>(x, WffE, WffI);
    zero_kernel<<<512, 512>>>();

    for (int t = 0; t < STEPS; t++) {
        step_kernel<<<dim3(NTOT / 64, BB / 64), 128>>>(t & 1, t);
    }

    fin_kernel<<<(BB * NTOT + 511) / 512, 512>>>(out);
}

// round 3
// speedup vs baseline: 1.6662x; 1.6662x over previous
#include <cuda_runtime.h>
#include <cuda_bf16.h>
#include <cstdint>

#define BB    256
#define NE    1024
#define NTOT  2048
#define DD    256
#define STEPS 200
#define LASTN 50

// ---------------- device scratch ----------------
__device__ __nv_bfloat16 g_Whi[NTOT * NTOT];
__device__ __nv_bfloat16 g_Wlo[NTOT * NTOT];
__device__ float g_Iff[BB * NTOT];
__device__ float g_r[2][BB * NTOT];                   // f32 state (for Euler update)
__device__ __nv_bfloat16 g_rhi[2][BB * NTOT];         // pre-split state, hi
__device__ __nv_bfloat16 g_rlo[2][BB * NTOT];         // pre-split state, lo
__device__ float g_acc[BB * NTOT];

// ---------------- weight prep (unchanged, proven) ----------------
__global__ void prep_w_kernel(const float* __restrict__ WEE,
                              const float* __restrict__ WEI,
                              const float* __restrict__ WIE,
                              const float* __restrict__ WII) {
    __shared__ float red[256];
    int j = blockIdx.x;
    int tid = threadIdx.x;
    bool isE = (j < NE);
    const float* rawA;
    const float* rawB;
    float SA, SB;
    if (isE) {
        rawA = WEE + (size_t)j * NE;  SA = 3.75f;
        rawB = WEI + (size_t)j * NE;  SB = 1.86f;
    } else {
        int j2 = j - NE;
        rawA = WIE + (size_t)j2 * NE; SA = 3.13f;
        rawB = WII + (size_t)j2 * NE; SB = 1.11f - 0.02f;
    }
    float sA = 0.f, sB = 0.f;
    for (int k = tid; k < NE; k += 256) { sA += rawA[k]; sB += rawB[k]; }
    red[tid] = sA; __syncthreads();
    for (int s = 128; s > 0; s >>= 1) { if (tid < s) red[tid] += red[tid + s]; __syncthreads(); }
    float sumA = red[0]; __syncthreads();
    red[tid] = sB; __syncthreads();
    for (int s = 128; s > 0; s >>= 1) { if (tid < s) red[tid] += red[tid + s]; __syncthreads(); }
    float sumB = red[0];

    float gA = SA / (sumA + 1e-12f);
    float gB = SB / (sumB + 1e-12f);

    for (int k = tid; k < NE; k += 256) {
        float a = rawA[k];
        if (isE) a = fminf(a, 0.15f);
        a *= gA;
        __nv_bfloat16 ha = __float2bfloat16_rn(a);
        g_Whi[j * NTOT + k] = ha;
        g_Wlo[j * NTOT + k] = __float2bfloat16_rn(a - __bfloat162float(ha));

        float b = rawB[k];
        if (isE) b = fmaxf(b, 0.0005f);
        b = -b * gB;
        __nv_bfloat16 hb = __float2bfloat16_rn(b);
        g_Whi[j * NTOT + NE + k] = hb;
        g_Wlo[j * NTOT + NE + k] = __float2bfloat16_rn(b - __bfloat162float(hb));
    }
}

// ---------------- feed-forward currents ----------------
__global__ void iff_kernel(const float* __restrict__ x,
                           const float* __restrict__ WffE,
                           const float* __restrict__ WffI) {
    __shared__ float sx[16][DD];
    int tid = threadIdx.x;
    int jblk = blockIdx.x * 256;
    int bblk = blockIdx.y * 16;
    for (int i = 0; i < 16; i++) sx[i][tid] = x[(bblk + i) * DD + tid];
    __syncthreads();
    int j = jblk + tid;
    const float* wr = (j < NE) ? (WffE + (size_t)j * DD) : (WffI + (size_t)(j - NE) * DD);
    float acc[16];
#pragma unroll
    for (int b = 0; b < 16; b++) acc[b] = 0.f;
    for (int d = 0; d < DD; d++) {
        float wv = __ldg(wr + d);
#pragma unroll
        for (int b = 0; b < 16; b++) acc[b] += sx[b][d] * wv;
    }
    for (int b = 0; b < 16; b++) g_Iff[(bblk + b) * NTOT + j] = acc[b];
}

// ---------------- zero init (graph replays) ----------------
__global__ void zero_kernel() {
    int i = blockIdx.x * blockDim.x + threadIdx.x;
    int stride = gridDim.x * blockDim.x;
    const __nv_bfloat16 z16 = __float2bfloat16_rn(0.f);
    for (int k = i; k < BB * NTOT; k += stride) {
        g_r[0][k] = 0.f;  g_r[1][k] = 0.f;
        g_rhi[0][k] = z16; g_rhi[1][k] = z16;
        g_rlo[0][k] = z16; g_rlo[1][k] = z16;
        g_acc[k] = 0.f;
    }
}

// ---------------- helpers ----------------
__device__ __forceinline__ void mma_bf16(float* c, const uint32_t* a, const uint32_t* b) {
    asm volatile(
        "mma.sync.aligned.m16n8k16.row.col.f32.bf16.bf16.f32 "
        "{%0,%1,%2,%3}, {%4,%5,%6,%7}, {%8,%9}, {%0,%1,%2,%3};\n"
        : "+f"(c[0]), "+f"(c[1]), "+f"(c[2]), "+f"(c[3])
        : "r"(a[0]), "r"(a[1]), "r"(a[2]), "r"(a[3]), "r"(b[0]), "r"(b[1]));
}

__device__ __forceinline__ void cpa16(uint32_t saddr, const void* gaddr) {
    asm volatile("cp.async.cg.shared.global [%0], [%1], 16;\n" :: "r"(saddr), "l"(gaddr));
}
__device__ __forceinline__ void cpa_commit() {
    asm volatile("cp.async.commit_group;\n" ::: "memory");
}
template <int N>
__device__ __forceinline__ void cpa_wait() {
    asm volatile("cp.async.wait_group %0;\n" :: "n"(N) : "memory");
}

// ---------------- one dynamics step ----------------
// CTA tile 32(M) x 64(N), K-step 32, 2-stage cp.async pipeline, 4 warps (warp tile 32x16).
// grid (2048/64, 256/32) = (32, 8) = 256 CTAs.
#define KS   32
#define PADC 40   // bf16 elements per smem row (80B, multiple of 16B for cp.async)

__global__ __launch_bounds__(128) void step_kernel(int parity, int t) {
    const float*         __restrict__ rin_f  = g_r[parity];
    float*               __restrict__ rout_f = g_r[parity ^ 1];
    const __nv_bfloat16* __restrict__ rhi_in = g_rhi[parity];
    const __nv_bfloat16* __restrict__ rlo_in = g_rlo[parity];
    __nv_bfloat16*       __restrict__ rhi_out = g_rhi[parity ^ 1];
    __nv_bfloat16*       __restrict__ rlo_out = g_rlo[parity ^ 1];

    __shared__ __align__(16) __nv_bfloat16 sAhi[2][32][PADC], sAlo[2][32][PADC];
    __shared__ __align__(16) __nv_bfloat16 sBhi[2][64][PADC], sBlo[2][64][PADC];

    int tid = threadIdx.x;
    int n0 = blockIdx.x * 64;
    int m0 = blockIdx.y * 32;
    int warp = tid >> 5, lane = tid & 31;
    int wn = warp << 4;              // warp N offset within tile
    int g = lane >> 2, tg = lane & 3;

    // cp.async thread mapping
    int aR = tid >> 2;               // 0..31
    int aC = (tid & 3) << 3;         // 0,8,16,24 (bf16)
    const __nv_bfloat16* aSrcHi = rhi_in + (size_t)(m0 + aR) * NTOT + aC;
    const __nv_bfloat16* aSrcLo = rlo_in + (size_t)(m0 + aR) * NTOT + aC;
    uint32_t aDstHi = (uint32_t)__cvta_generic_to_shared(&sAhi[0][aR][aC]);
    uint32_t aDstLo = (uint32_t)__cvta_generic_to_shared(&sAlo[0][aR][aC]);

    int bR0 = tid >> 2;              // 0..31
    int bR1 = bR0 + 32;              // 32..63
    int bC = (tid & 3) << 3;
    const __nv_bfloat16* bSrcHi0 = g_Whi + (size_t)(n0 + bR0) * NTOT + bC;
    const __nv_bfloat16* bSrcHi1 = g_Whi + (size_t)(n0 + bR1) * NTOT + bC;
    const __nv_bfloat16* bSrcLo0 = g_Wlo + (size_t)(n0 + bR0) * NTOT + bC;
    const __nv_bfloat16* bSrcLo1 = g_Wlo + (size_t)(n0 + bR1) * NTOT + bC;
    uint32_t bDstHi0 = (uint32_t)__cvta_generic_to_shared(&sBhi[0][bR0][bC]);
    uint32_t bDstHi1 = (uint32_t)__cvta_generic_to_shared(&sBhi[0][bR1][bC]);
    uint32_t bDstLo0 = (uint32_t)__cvta_generic_to_shared(&sBlo[0][bR0][bC]);
    uint32_t bDstLo1 = (uint32_t)__cvta_generic_to_shared(&sBlo[0][bR1][bC]);

    const uint32_t A_STAGE = 32 * PADC * 2;   // bytes per A stage
    const uint32_t B_STAGE = 64 * PADC * 2;

    float acc[2][2][4];
#pragma unroll
    for (int mt = 0; mt < 2; mt++)
#pragma unroll
        for (int nt = 0; nt < 2; nt++)
#pragma unroll
            for (int q = 0; q < 4; q++) acc[mt][nt][q] = 0.f;

    // prologue: stage 0
    {
        cpa16(aDstHi, aSrcHi);
        cpa16(aDstLo, aSrcLo);
        cpa16(bDstHi0, bSrcHi0);
        cpa16(bDstHi1, bSrcHi1);
        cpa16(bDstLo0, bSrcLo0);
        cpa16(bDstLo1, bSrcLo1);
        cpa_commit();
    }

#pragma unroll 1
    for (int ks = 0; ks < NTOT / KS; ks++) {
        int buf = ks & 1;
        if (ks + 1 < NTOT / KS) {
            int k1 = (ks + 1) * KS;
            uint32_t so = (buf ^ 1) ? 1u : 0u;
            cpa16(aDstHi + so * A_STAGE, aSrcHi + k1);
            cpa16(aDstLo + so * A_STAGE, aSrcLo + k1);
            cpa16(bDstHi0 + so * B_STAGE, bSrcHi0 + k1);
            cpa16(bDstHi1 + so * B_STAGE, bSrcHi1 + k1);
            cpa16(bDstLo0 + so * B_STAGE, bSrcLo0 + k1);
            cpa16(bDstLo1 + so * B_STAGE, bSrcLo1 + k1);
            cpa_commit();
            cpa_wait<1>();
        } else {
            cpa_wait<0>();
        }
        __syncthreads();

#pragma unroll
        for (int kb = 0; kb < KS; kb += 16) {
            int c0 = kb + (tg << 1);
            uint32_t ah[2][4], al[2][4], bh[2][2], bl[2][2];
#pragma unroll
            for (int mt = 0; mt < 2; mt++) {
                int r0 = (mt << 4) + g;
                ah[mt][0] = *(const uint32_t*)&sAhi[buf][r0][c0];
                ah[mt][1] = *(const uint32_t*)&sAhi[buf][r0 + 8][c0];
                ah[mt][2] = *(const uint32_t*)&sAhi[buf][r0][c0 + 8];
                ah[mt][3] = *(const uint32_t*)&sAhi[buf][r0 + 8][c0 + 8];
                al[mt][0] = *(const uint32_t*)&sAlo[buf][r0][c0];
                al[mt][1] = *(const uint32_t*)&sAlo[buf][r0 + 8][c0];
                al[mt][2] = *(const uint32_t*)&sAlo[buf][r0][c0 + 8];
                al[mt][3] = *(const uint32_t*)&sAlo[buf][r0 + 8][c0 + 8];
            }
#pragma unroll
            for (int nt = 0; nt < 2; nt++) {
                int nr = wn + (nt << 3) + g;
                bh[nt][0] = *(const uint32_t*)&sBhi[buf][nr][c0];
                bh[nt][1] = *(const uint32_t*)&sBhi[buf][nr][c0 + 8];
                bl[nt][0] = *(const uint32_t*)&sBlo[buf][nr][c0];
                bl[nt][1] = *(const uint32_t*)&sBlo[buf][nr][c0 + 8];
            }
            // hh pass (independent chains), then cross terms
#pragma unroll
            for (int mt = 0; mt < 2; mt++)
#pragma unroll
                for (int nt = 0; nt < 2; nt++) mma_bf16(acc[mt][nt], ah[mt], bh[nt]);
#pragma unroll
            for (int mt = 0; mt < 2; mt++)
#pragma unroll
                for (int nt = 0; nt < 2; nt++) mma_bf16(acc[mt][nt], ah[mt], bl[nt]);
#pragma unroll
            for (int mt = 0; mt < 2; mt++)
#pragma unroll
                for (int nt = 0; nt < 2; nt++) mma_bf16(acc[mt][nt], al[mt], bh[nt]);
        }
        __syncthreads();
    }

    // epilogue
#pragma unroll
    for (int mt = 0; mt < 2; mt++) {
#pragma unroll
        for (int nt = 0; nt < 2; nt++) {
            int colb = n0 + wn + (nt << 3) + (tg << 1);
            float rate = (colb < NE) ? 0.05f : 0.1f;
#pragma unroll
            for (int h = 0; h < 2; h++) {
                int row = m0 + (mt << 4) + g + (h << 3);
                size_t idx = (size_t)row * NTOT + colb;
                float2 iff = *(const float2*)&g_Iff[idx];
                float2 ro  = *(const float2*)&rin_f[idx];
                float I0 = acc[mt][nt][h * 2 + 0] + iff.x;
                float I1 = acc[mt][nt][h * 2 + 1] + iff.y;
                float rl0 = fmaxf(I0, 0.f), rl1 = fmaxf(I1, 0.f);
                float f0 = 0.04f * rl0 * rl0, f1 = 0.04f * rl1 * rl1;
                float rn0 = fmaf(rate, f0 - ro.x, ro.x);
                float rn1 = fmaf(rate, f1 - ro.y, ro.y);
                float2 rn2; rn2.x = rn0; rn2.y = rn1;
                *(float2*)&rout_f[idx] = rn2;
                __nv_bfloat16 h0 = __float2bfloat16_rn(rn0);
                __nv_bfloat16 h1 = __float2bfloat16_rn(rn1);
                __nv_bfloat16 l0 = __float2bfloat16_rn(rn0 - __bfloat162float(h0));
                __nv_bfloat16 l1 = __float2bfloat16_rn(rn1 - __bfloat162float(h1));
                uint32_t hp = (uint32_t)*(uint16_t*)&h0 | ((uint32_t)*(uint16_t*)&h1 << 16);
                uint32_t lp = (uint32_t)*(uint16_t*)&l0 | ((uint32_t)*(uint16_t*)&l1 << 16);
                *(uint32_t*)&rhi_out[idx] = hp;
                *(uint32_t*)&rlo_out[idx] = lp;
                if (t >= STEPS - LASTN) {
                    float2 a = *(float2*)&g_acc[idx];
                    a.x += rn0; a.y += rn1;
                    *(float2*)&g_acc[idx] = a;
                }
            }
        }
    }
}

// ---------------- finalize ----------------
__global__ void fin_kernel(float* __restrict__ out) {
    int i = blockIdx.x * blockDim.x + threadIdx.x;
    if (i < BB * NTOT) {
        int b = i >> 11;
        int j = i & 2047;
        float v = g_acc[i] * (1.0f / (float)LASTN);
        if (j < NE) out[b * NE + j] = v;
        else        out[BB * NE + b * NE + (j - NE)] = v;
    }
}

// ---------------- launch ----------------
extern "C" void kernel_launch(void* const* d_in, const int* in_sizes, int n_in,
                              void* d_out, int out_size) {
    const float* x    = (const float*)d_in[0];
    const float* WEE  = (const float*)d_in[1];
    const float* WEI  = (const float*)d_in[2];
    const float* WIE  = (const float*)d_in[3];
    const float* WII  = (const float*)d_in[4];
    const float* WffE = (const float*)d_in[5];
    const float* WffI = (const float*)d_in[6];
    float* out = (float*)d_out;

    prep_w_kernel<<<NTOT, 256>>>(WEE, WEI, WIE, WII);
    iff_kernel<<<dim3(NTOT / 256, BB / 16), 256>>>(x, WffE, WffI);
    zero_kernel<<<512, 512>>>();

    for (int t = 0; t < STEPS; t++) {
        step_kernel<<<dim3(NTOT / 64, BB / 32), 128>>>(t & 1, t);
    }

    fin_kernel<<<(BB * NTOT + 511) / 512, 512>>>(out);
}

// round 5
// speedup vs baseline: 2.1337x; 1.2806x over previous
#include <cuda_runtime.h>
#include <cuda_bf16.h>
#include <cstdint>

#define BB    256
#define NE    1024
#define NTOT  2048
#define DD    256
#define STEPS 200
#define LASTN 50

// step kernel geometry
#define KS     64            // K-slab
#define PITCHB 144           // bytes per smem row (64 bf16 = 128B + 16B pad)
#define STAGE_BYTES (64 * PITCHB)              // one stage of one matrix: 9216B
#define SMEM_TOTAL  (4 * 2 * STAGE_BYTES)      // 4 matrices x 2 stages = 73728B

// ---------------- device scratch ----------------
__device__ __nv_bfloat16 g_Whi[NTOT * NTOT];
__device__ __nv_bfloat16 g_Wlo[NTOT * NTOT];
__device__ float g_Iff[BB * NTOT];
__device__ float g_r[2][BB * NTOT];
__device__ __nv_bfloat16 g_rhi[2][BB * NTOT];
__device__ __nv_bfloat16 g_rlo[2][BB * NTOT];
__device__ float g_acc[BB * NTOT];

// ---------------- weight prep (proven) ----------------
__global__ void prep_w_kernel(const float* __restrict__ WEE,
                              const float* __restrict__ WEI,
                              const float* __restrict__ WIE,
                              const float* __restrict__ WII) {
    __shared__ float red[256];
    int j = blockIdx.x;
    int tid = threadIdx.x;
    bool isE = (j < NE);
    const float* rawA;
    const float* rawB;
    float SA, SB;
    if (isE) {
        rawA = WEE + (size_t)j * NE;  SA = 3.75f;
        rawB = WEI + (size_t)j * NE;  SB = 1.86f;
    } else {
        int j2 = j - NE;
        rawA = WIE + (size_t)j2 * NE; SA = 3.13f;
        rawB = WII + (size_t)j2 * NE; SB = 1.11f - 0.02f;
    }
    float sA = 0.f, sB = 0.f;
    for (int k = tid; k < NE; k += 256) { sA += rawA[k]; sB += rawB[k]; }
    red[tid] = sA; __syncthreads();
    for (int s = 128; s > 0; s >>= 1) { if (tid < s) red[tid] += red[tid + s]; __syncthreads(); }
    float sumA = red[0]; __syncthreads();
    red[tid] = sB; __syncthreads();
    for (int s = 128; s > 0; s >>= 1) { if (tid < s) red[tid] += red[tid + s]; __syncthreads(); }
    float sumB = red[0];

    float gA = SA / (sumA + 1e-12f);
    float gB = SB / (sumB + 1e-12f);

    for (int k = tid; k < NE; k += 256) {
        float a = rawA[k];
        if (isE) a = fminf(a, 0.15f);
        a *= gA;
        __nv_bfloat16 ha = __float2bfloat16_rn(a);
        g_Whi[j * NTOT + k] = ha;
        g_Wlo[j * NTOT + k] = __float2bfloat16_rn(a - __bfloat162float(ha));

        float b = rawB[k];
        if (isE) b = fmaxf(b, 0.0005f);
        b = -b * gB;
        __nv_bfloat16 hb = __float2bfloat16_rn(b);
        g_Whi[j * NTOT + NE + k] = hb;
        g_Wlo[j * NTOT + NE + k] = __float2bfloat16_rn(b - __bfloat162float(hb));
    }
}

// ---------------- feed-forward currents ----------------
__global__ void iff_kernel(const float* __restrict__ x,
                           const float* __restrict__ WffE,
                           const float* __restrict__ WffI) {
    __shared__ float sx[16][DD];
    int tid = threadIdx.x;
    int jblk = blockIdx.x * 256;
    int bblk = blockIdx.y * 16;
    for (int i = 0; i < 16; i++) sx[i][tid] = x[(bblk + i) * DD + tid];
    __syncthreads();
    int j = jblk + tid;
    const float* wr = (j < NE) ? (WffE + (size_t)j * DD) : (WffI + (size_t)(j - NE) * DD);
    float acc[16];
#pragma unroll
    for (int b = 0; b < 16; b++) acc[b] = 0.f;
    for (int d = 0; d < DD; d++) {
        float wv = __ldg(wr + d);
#pragma unroll
        for (int b = 0; b < 16; b++) acc[b] += sx[b][d] * wv;
    }
    for (int b = 0; b < 16; b++) g_Iff[(bblk + b) * NTOT + j] = acc[b];
}

// ---------------- zero init ----------------
__global__ void zero_kernel() {
    int i = blockIdx.x * blockDim.x + threadIdx.x;
    int stride = gridDim.x * blockDim.x;
    const __nv_bfloat16 z16 = __float2bfloat16_rn(0.f);
    for (int k = i; k < BB * NTOT; k += stride) {
        g_r[0][k] = 0.f;  g_r[1][k] = 0.f;
        g_rhi[0][k] = z16; g_rhi[1][k] = z16;
        g_rlo[0][k] = z16; g_rlo[1][k] = z16;
        g_acc[k] = 0.f;
    }
}

// ---------------- helpers ----------------
__device__ __forceinline__ void mma_bf16(float* c, const uint32_t* a, const uint32_t* b) {
    asm volatile(
        "mma.sync.aligned.m16n8k16.row.col.f32.bf16.bf16.f32 "
        "{%0,%1,%2,%3}, {%4,%5,%6,%7}, {%8,%9}, {%0,%1,%2,%3};\n"
        : "+f"(c[0]), "+f"(c[1]), "+f"(c[2]), "+f"(c[3])
        : "r"(a[0]), "r"(a[1]), "r"(a[2]), "r"(a[3]), "r"(b[0]), "r"(b[1]));
}

__device__ __forceinline__ void ldsm4(uint32_t* r, uint32_t addr) {
    asm volatile("ldmatrix.sync.aligned.m8n8.x4.shared.b16 {%0,%1,%2,%3}, [%4];\n"
                 : "=r"(r[0]), "=r"(r[1]), "=r"(r[2]), "=r"(r[3]) : "r"(addr));
}

__device__ __forceinline__ void cpa16(uint32_t saddr, const void* gaddr) {
    asm volatile("cp.async.cg.shared.global [%0], [%1], 16;\n" :: "r"(saddr), "l"(gaddr));
}
__device__ __forceinline__ void cpa_commit() {
    asm volatile("cp.async.commit_group;\n" ::: "memory");
}
__device__ __forceinline__ void cpa_wait_all() {
    asm volatile("cp.async.wait_group 0;\n" ::: "memory");
}

// ---------------- one dynamics step ----------------
// CTA tile 64(M) x 64(N), 256 threads = 8 warps (2M x 4N), warp tile 32x16.
// K-slab 64, 2-stage cp.async pipeline, one __syncthreads per slab, ldmatrix frags.
// grid (2048/64, 256/64) = (32, 4) = 128 CTAs.
__global__ __launch_bounds__(256) void step_kernel(int parity, int t) {
    const float*         __restrict__ rin_f   = g_r[parity];
    float*               __restrict__ rout_f  = g_r[parity ^ 1];
    const __nv_bfloat16* __restrict__ rhi_in  = g_rhi[parity];
    const __nv_bfloat16* __restrict__ rlo_in  = g_rlo[parity];
    __nv_bfloat16*       __restrict__ rhi_out = g_rhi[parity ^ 1];
    __nv_bfloat16*       __restrict__ rlo_out = g_rlo[parity ^ 1];

    extern __shared__ __align__(16) unsigned char smraw[];
    const uint32_t S0 = (uint32_t)__cvta_generic_to_shared(smraw);
    const uint32_t A_HI = S0;
    const uint32_t A_LO = S0 + 2 * STAGE_BYTES;
    const uint32_t B_HI = S0 + 4 * STAGE_BYTES;
    const uint32_t B_LO = S0 + 6 * STAGE_BYTES;

    int tid = threadIdx.x;
    int lane = tid & 31, warp = tid >> 5;
    int n0 = blockIdx.x * 64;
    int m0 = blockIdx.y * 64;
    int wm = (warp >> 2) << 5;     // 0 / 32
    int wn = (warp & 3) << 4;      // 0..48
    int g = lane >> 2, tg = lane & 3;

    // ---- cp.async mapping: chunk = tid (+256); row = chunk>>3, col = (chunk&7)*16B
    int cr = tid >> 3;             // rows 0..31 (second chunk: +32)
    int cc = (tid & 7) << 3;       // element offset (bf16), *2 = bytes
    uint32_t dOff0 = (uint32_t)cr * PITCHB + (cc << 1);
    uint32_t dOff1 = (uint32_t)(cr + 32) * PITCHB + (cc << 1);
    const __nv_bfloat16* aHiS0 = rhi_in + (size_t)(m0 + cr) * NTOT + cc;
    const __nv_bfloat16* aHiS1 = rhi_in + (size_t)(m0 + cr + 32) * NTOT + cc;
    const __nv_bfloat16* aLoS0 = rlo_in + (size_t)(m0 + cr) * NTOT + cc;
    const __nv_bfloat16* aLoS1 = rlo_in + (size_t)(m0 + cr + 32) * NTOT + cc;
    const __nv_bfloat16* bHiS0 = g_Whi + (size_t)(n0 + cr) * NTOT + cc;
    const __nv_bfloat16* bHiS1 = g_Whi + (size_t)(n0 + cr + 32) * NTOT + cc;
    const __nv_bfloat16* bLoS0 = g_Wlo + (size_t)(n0 + cr) * NTOT + cc;
    const __nv_bfloat16* bLoS1 = g_Wlo + (size_t)(n0 + cr + 32) * NTOT + cc;

    // ---- ldmatrix per-lane offsets
    // A tiles: reg0 [r0..7][k0..7], reg1 [r0+8..15][k0..7], reg2 [r0..7][k8..15], reg3 [+8][+8]
    int aRow = (lane & 7) + (((lane >> 3) & 1) << 3);
    int aCol = ((lane >> 4) << 3);
    // B tiles: reg0 [n0..7][k0..7], reg1 [n0..7][k8..15], reg2 [n8..15][k0..7], reg3 [+8][+8]
    int bRow = (lane & 7) + ((lane >> 4) << 3);
    int bCol = (((lane >> 3) & 1) << 3);

    uint32_t aHiAddr0 = A_HI + (uint32_t)(wm + aRow) * PITCHB + (aCol << 1);
    uint32_t aHiAddr1 = A_HI + (uint32_t)(wm + 16 + aRow) * PITCHB + (aCol << 1);
    uint32_t aLoAddr0 = A_LO + (uint32_t)(wm + aRow) * PITCHB + (aCol << 1);
    uint32_t aLoAddr1 = A_LO + (uint32_t)(wm + 16 + aRow) * PITCHB + (aCol << 1);
    uint32_t bHiAddr  = B_HI + (uint32_t)(wn + bRow) * PITCHB + (bCol << 1);
    uint32_t bLoAddr  = B_LO + (uint32_t)(wn + bRow) * PITCHB + (bCol << 1);

    float acc[2][2][4];
#pragma unroll
    for (int mt = 0; mt < 2; mt++)
#pragma unroll
        for (int nt = 0; nt < 2; nt++)
#pragma unroll
            for (int q = 0; q < 4; q++) acc[mt][nt][q] = 0.f;

    // prologue: stage 0 into buf 0
    {
        cpa16(A_HI + dOff0, aHiS0);
        cpa16(A_HI + dOff1, aHiS1);
        cpa16(A_LO + dOff0, aLoS0);
        cpa16(A_LO + dOff1, aLoS1);
        cpa16(B_HI + dOff0, bHiS0);
        cpa16(B_HI + dOff1, bHiS1);
        cpa16(B_LO + dOff0, bLoS0);
        cpa16(B_LO + dOff1, bLoS1);
        cpa_commit();
    }

#pragma unroll 1
    for (int ks = 0; ks < NTOT / KS; ks++) {
        int buf = ks & 1;
        uint32_t so = (uint32_t)buf * STAGE_BYTES;

        cpa_wait_all();          // stage ks resident
        __syncthreads();         // all warps done with buf^1 (previous compute)

        if (ks + 1 < NTOT / KS) {
            int k1 = (ks + 1) * KS;
            uint32_t po = (uint32_t)(buf ^ 1) * STAGE_BYTES;
            cpa16(A_HI + po + dOff0, aHiS0 + k1);
            cpa16(A_HI + po + dOff1, aHiS1 + k1);
            cpa16(A_LO + po + dOff0, aLoS0 + k1);
            cpa16(A_LO + po + dOff1, aLoS1 + k1);
            cpa16(B_HI + po + dOff0, bHiS0 + k1);
            cpa16(B_HI + po + dOff1, bHiS1 + k1);
            cpa16(B_LO + po + dOff0, bLoS0 + k1);
            cpa16(B_LO + po + dOff1, bLoS1 + k1);
            cpa_commit();
        }

#pragma unroll
        for (int kb = 0; kb < KS; kb += 16) {
            uint32_t ko = (uint32_t)kb << 1;   // bytes
            uint32_t ah[2][4], al[2][4], bh[4], bl[4];
            ldsm4(ah[0], aHiAddr0 + so + ko);
            ldsm4(ah[1], aHiAddr1 + so + ko);
            ldsm4(al[0], aLoAddr0 + so + ko);
            ldsm4(al[1], aLoAddr1 + so + ko);
            ldsm4(bh, bHiAddr + so + ko);
            ldsm4(bl, bLoAddr + so + ko);
#pragma unroll
            for (int mt = 0; mt < 2; mt++)
#pragma unroll
                for (int nt = 0; nt < 2; nt++) mma_bf16(acc[mt][nt], ah[mt], &bh[nt << 1]);
#pragma unroll
            for (int mt = 0; mt < 2; mt++)
#pragma unroll
                for (int nt = 0; nt < 2; nt++) mma_bf16(acc[mt][nt], ah[mt], &bl[nt << 1]);
#pragma unroll
            for (int mt = 0; mt < 2; mt++)
#pragma unroll
                for (int nt = 0; nt < 2; nt++) mma_bf16(acc[mt][nt], al[mt], &bh[nt << 1]);
        }
        // no trailing sync: next iteration's barrier protects the buffer swap
    }

    // epilogue
#pragma unroll
    for (int mt = 0; mt < 2; mt++) {
#pragma unroll
        for (int nt = 0; nt < 2; nt++) {
            int colb = n0 + wn + (nt << 3) + (tg << 1);
            float rate = (colb < NE) ? 0.05f : 0.1f;
#pragma unroll
            for (int h = 0; h < 2; h++) {
                int row = m0 + wm + (mt << 4) + g + (h << 3);
                size_t idx = (size_t)row * NTOT + colb;
                float2 iff = *(const float2*)&g_Iff[idx];
                float2 ro  = *(const float2*)&rin_f[idx];
                float I0 = acc[mt][nt][h * 2 + 0] + iff.x;
                float I1 = acc[mt][nt][h * 2 + 1] + iff.y;
                float rl0 = fmaxf(I0, 0.f), rl1 = fmaxf(I1, 0.f);
                float f0 = 0.04f * rl0 * rl0, f1 = 0.04f * rl1 * rl1;
                float rn0 = fmaf(rate, f0 - ro.x, ro.x);
                float rn1 = fmaf(rate, f1 - ro.y, ro.y);
                float2 rn2; rn2.x = rn0; rn2.y = rn1;
                *(float2*)&rout_f[idx] = rn2;
                __nv_bfloat16 h0 = __float2bfloat16_rn(rn0);
                __nv_bfloat16 h1 = __float2bfloat16_rn(rn1);
                __nv_bfloat16 l0 = __float2bfloat16_rn(rn0 - __bfloat162float(h0));
                __nv_bfloat16 l1 = __float2bfloat16_rn(rn1 - __bfloat162float(h1));
                uint32_t hp = (uint32_t)*(uint16_t*)&h0 | ((uint32_t)*(uint16_t*)&h1 << 16);
                uint32_t lp = (uint32_t)*(uint16_t*)&l0 | ((uint32_t)*(uint16_t*)&l1 << 16);
                *(uint32_t*)&rhi_out[idx] = hp;
                *(uint32_t*)&rlo_out[idx] = lp;
                if (t >= STEPS - LASTN) {
                    float2 a = *(float2*)&g_acc[idx];
                    a.x += rn0; a.y += rn1;
                    *(float2*)&g_acc[idx] = a;
                }
            }
        }
    }
}

// ---------------- finalize ----------------
__global__ void fin_kernel(float* __restrict__ out) {
    int i = blockIdx.x * blockDim.x + threadIdx.x;
    if (i < BB * NTOT) {
        int b = i >> 11;
        int j = i & 2047;
        float v = g_acc[i] * (1.0f / (float)LASTN);
        if (j < NE) out[b * NE + j] = v;
        else        out[BB * NE + b * NE + (j - NE)] = v;
    }
}

// ---------------- launch ----------------
extern "C" void kernel_launch(void* const* d_in, const int* in_sizes, int n_in,
                              void* d_out, int out_size) {
    const float* x    = (const float*)d_in[0];
    const float* WEE  = (const float*)d_in[1];
    const float* WEI  = (const float*)d_in[2];
    const float* WIE  = (const float*)d_in[3];
    const float* WII  = (const float*)d_in[4];
    const float* WffE = (const float*)d_in[5];
    const float* WffI = (const float*)d_in[6];
    float* out = (float*)d_out;

    cudaFuncSetAttribute(step_kernel, cudaFuncAttributeMaxDynamicSharedMemorySize, SMEM_TOTAL);

    prep_w_kernel<<<NTOT, 256>>>(WEE, WEI, WIE, WII);
    iff_kernel<<<dim3(NTOT / 256, BB / 16), 256>>>(x, WffE, WffI);
    zero_kernel<<<512, 512>>>();

    for (int t = 0; t < STEPS; t++) {
        step_kernel<<<dim3(NTOT / 64, BB / 64), 256, SMEM_TOTAL>>>(t & 1, t);
    }

    fin_kernel<<<(BB * NTOT + 511) / 512, 512>>>(out);
}